// round 3
// baseline (speedup 1.0000x reference)
#include <cuda_runtime.h>
#include <math.h>

#define S_TOK 32
#define H_DIM 768
#define I_DIM 768
#define E_NUM 32
#define K_TOP 4
#define TWO_I 1536
#define LIMIT 7.0f
#define ALPHA 1.702f
#define EPS 1e-5f
#define TMAX 8   // tokens resident in SMEM per pass

// -------- device scratch --------
__device__ float g_t[S_TOK][H_DIM];
__device__ int   g_topk_idx[S_TOK][K_TOP];
__device__ float g_topk_w[S_TOK][K_TOP];
__device__ int   g_cnt[E_NUM];
__device__ int   g_tok[E_NUM][S_TOK];
__device__ float g_ew[E_NUM][S_TOK];
__device__ float g_act[E_NUM][S_TOK][I_DIM];

// ======================================================================
// Kernel 1: RMSNorm + residual init + router logits + top-4 + softmax
// ======================================================================
__global__ void __launch_bounds__(256) k_route(
    const float* __restrict__ x, const float* __restrict__ norm_scale,
    const float* __restrict__ gate_w, const float* __restrict__ gate_b,
    float* __restrict__ out)
{
    int s   = blockIdx.x;
    int tid = threadIdx.x;
    int lane = tid & 31, warp = tid >> 5;

    __shared__ float sh_t[H_DIM];
    __shared__ float sh_red[8];
    __shared__ float sh_g[E_NUM];

    float ss = 0.f;
    for (int c = tid; c < H_DIM; c += 256) {
        float v = x[s * H_DIM + c];
        sh_t[c] = v;
        out[s * H_DIM + c] = v;          // residual
        ss += v * v;
    }
    #pragma unroll
    for (int o = 16; o; o >>= 1) ss += __shfl_xor_sync(0xffffffffu, ss, o);
    if (lane == 0) sh_red[warp] = ss;
    __syncthreads();
    if (tid < 8) {
        float v = sh_red[tid];
        #pragma unroll
        for (int o = 4; o; o >>= 1) v += __shfl_xor_sync(0xffu, v, o);
        if (tid == 0) sh_red[0] = v;
    }
    __syncthreads();
    float rms = rsqrtf(sh_red[0] / (float)H_DIM + EPS);

    for (int c = tid; c < H_DIM; c += 256) {
        float tv = sh_t[c] * rms * norm_scale[c];
        sh_t[c] = tv;
        g_t[s][c] = tv;
    }
    __syncthreads();

    #pragma unroll
    for (int q = 0; q < 4; q++) {
        int e = warp * 4 + q;
        const float* gwr = gate_w + (size_t)e * H_DIM;
        float acc = 0.f;
        for (int c = lane; c < H_DIM; c += 32) acc += sh_t[c] * gwr[c];
        #pragma unroll
        for (int o = 16; o; o >>= 1) acc += __shfl_xor_sync(0xffffffffu, acc, o);
        if (lane == 0) sh_g[e] = acc + gate_b[e];
    }
    __syncthreads();

    if (tid == 0) {
        bool used[E_NUM];
        #pragma unroll
        for (int e = 0; e < E_NUM; e++) used[e] = false;
        float vals[K_TOP]; int idx[K_TOP];
        for (int k = 0; k < K_TOP; k++) {
            float best = -1e30f; int bi = 0;
            for (int e = 0; e < E_NUM; e++)
                if (!used[e] && sh_g[e] > best) { best = sh_g[e]; bi = e; }
            used[bi] = true; vals[k] = best; idx[k] = bi;
        }
        float m = vals[0], sum = 0.f, w[K_TOP];
        for (int k = 0; k < K_TOP; k++) { w[k] = __expf(vals[k] - m); sum += w[k]; }
        for (int k = 0; k < K_TOP; k++) {
            g_topk_idx[s][k] = idx[k];
            g_topk_w[s][k]   = w[k] / sum;
        }
    }
}

// ======================================================================
// Kernel 2: group (token,k) pairs by expert
// ======================================================================
__global__ void k_group()
{
    if (blockIdx.x == 0 && threadIdx.x == 0) {
        int cnt[E_NUM];
        #pragma unroll
        for (int e = 0; e < E_NUM; e++) cnt[e] = 0;
        for (int s = 0; s < S_TOK; s++)
            for (int k = 0; k < K_TOP; k++) {
                int e = g_topk_idx[s][k];
                int slot = cnt[e]++;
                g_tok[e][slot] = s;
                g_ew[e][slot]  = g_topk_w[s][k];
            }
        for (int e = 0; e < E_NUM; e++) g_cnt[e] = cnt[e];
    }
}

// ======================================================================
// Kernel 3: w1 GEMV + SwiGLU. grid=(12,E); block covers 64 row-PAIRS
// (=128 rows). Warp handles one pair at a time; ALL np tokens are
// accumulated in a single pass over the weight rows (read-once).
// ======================================================================
__global__ void __launch_bounds__(256) k_w1(
    const float* __restrict__ w1, const float* __restrict__ b1)
{
    int e = blockIdx.y;
    int cnt = g_cnt[e];
    if (cnt == 0) return;

    int pairbase = blockIdx.x * 64;
    int tid = threadIdx.x, lane = tid & 31, warp = tid >> 5;

    __shared__ float sh_t[TMAX][H_DIM];

    const float* w1e = w1 + (size_t)e * TWO_I * H_DIM;

    for (int p0 = 0; p0 < cnt; p0 += TMAX) {
        int np = min(TMAX, cnt - p0);
        __syncthreads();
        for (int idx = tid; idx < np * H_DIM; idx += 256) {
            int j = idx / H_DIM, c = idx - j * H_DIM;
            sh_t[j][c] = g_t[g_tok[e][p0 + j]][c];
        }
        __syncthreads();

        for (int p = warp; p < 64; p += 8) {
            int pr = pairbase + p;
            int r0 = 2 * pr;
            const float4* wr0 = (const float4*)(w1e + (size_t)r0 * H_DIM);
            const float4* wr1 = (const float4*)(w1e + (size_t)(r0 + 1) * H_DIM);

            float a0[TMAX], a1[TMAX];
            #pragma unroll
            for (int j = 0; j < TMAX; j++) { a0[j] = 0.f; a1[j] = 0.f; }

            #pragma unroll 3
            for (int c = lane; c < H_DIM / 4; c += 32) {
                float4 wa = wr0[c];
                float4 wb = wr1[c];
                #pragma unroll
                for (int j = 0; j < TMAX; j++) {
                    if (j < np) {
                        float4 tv = *(const float4*)&sh_t[j][c * 4];
                        a0[j] += wa.x*tv.x + wa.y*tv.y + wa.z*tv.z + wa.w*tv.w;
                        a1[j] += wb.x*tv.x + wb.y*tv.y + wb.z*tv.z + wb.w*tv.w;
                    }
                }
            }
            #pragma unroll
            for (int j = 0; j < TMAX; j++) {
                if (j < np) {
                    #pragma unroll
                    for (int o = 16; o; o >>= 1) {
                        a0[j] += __shfl_xor_sync(0xffffffffu, a0[j], o);
                        a1[j] += __shfl_xor_sync(0xffffffffu, a1[j], o);
                    }
                }
            }
            float bg = b1[(size_t)e * TWO_I + r0];
            float bl = b1[(size_t)e * TWO_I + r0 + 1];
            #pragma unroll
            for (int j = 0; j < TMAX; j++) {
                if (j < np && lane == j) {   // compile-time j: no dynamic reg index
                    float hg = a0[j] + bg;
                    float hl = a1[j] + bl;
                    hg = fminf(hg, LIMIT);
                    hl = fminf(fmaxf(hl, -LIMIT), LIMIT);
                    float sg = 1.f / (1.f + __expf(-ALPHA * hg));
                    g_act[e][p0 + j][pr] = hg * sg * (hl + 1.f);
                }
            }
        }
    }
}

// ======================================================================
// Kernel 4: w2 GEMV + weighted atomic accumulate. grid=(12,E); block
// covers 32 row-pairs (=64 rows). Same read-once / row-pair structure.
// ======================================================================
__global__ void __launch_bounds__(256) k_w2(
    const float* __restrict__ w2, const float* __restrict__ b2,
    float* __restrict__ out)
{
    int e = blockIdx.y;
    int cnt = g_cnt[e];
    if (cnt == 0) return;

    int pairbase = blockIdx.x * 32;
    int tid = threadIdx.x, lane = tid & 31, warp = tid >> 5;

    __shared__ float sh_a[TMAX][I_DIM];
    __shared__ float sh_w[TMAX];
    __shared__ int   sh_tok[TMAX];

    const float* w2e = w2 + (size_t)e * H_DIM * I_DIM;

    for (int p0 = 0; p0 < cnt; p0 += TMAX) {
        int np = min(TMAX, cnt - p0);
        __syncthreads();
        for (int idx = tid; idx < np * I_DIM; idx += 256) {
            int j = idx / I_DIM, c = idx - j * I_DIM;
            sh_a[j][c] = g_act[e][p0 + j][c];
        }
        if (tid < np) {
            sh_w[tid]   = g_ew[e][p0 + tid];
            sh_tok[tid] = g_tok[e][p0 + tid];
        }
        __syncthreads();

        for (int p = warp; p < 32; p += 8) {
            int r0 = 2 * (pairbase + p);
            const float4* wr0 = (const float4*)(w2e + (size_t)r0 * I_DIM);
            const float4* wr1 = (const float4*)(w2e + (size_t)(r0 + 1) * I_DIM);

            float a0[TMAX], a1[TMAX];
            #pragma unroll
            for (int j = 0; j < TMAX; j++) { a0[j] = 0.f; a1[j] = 0.f; }

            #pragma unroll 3
            for (int c = lane; c < I_DIM / 4; c += 32) {
                float4 wa = wr0[c];
                float4 wb = wr1[c];
                #pragma unroll
                for (int j = 0; j < TMAX; j++) {
                    if (j < np) {
                        float4 av = *(const float4*)&sh_a[j][c * 4];
                        a0[j] += wa.x*av.x + wa.y*av.y + wa.z*av.z + wa.w*av.w;
                        a1[j] += wb.x*av.x + wb.y*av.y + wb.z*av.z + wb.w*av.w;
                    }
                }
            }
            #pragma unroll
            for (int j = 0; j < TMAX; j++) {
                if (j < np) {
                    #pragma unroll
                    for (int o = 16; o; o >>= 1) {
                        a0[j] += __shfl_xor_sync(0xffffffffu, a0[j], o);
                        a1[j] += __shfl_xor_sync(0xffffffffu, a1[j], o);
                    }
                }
            }
            float bb0 = b2[(size_t)e * H_DIM + r0];
            float bb1 = b2[(size_t)e * H_DIM + r0 + 1];
            #pragma unroll
            for (int j = 0; j < TMAX; j++) {
                if (j < np && lane == j) {
                    float ww = sh_w[j];
                    int   tk = sh_tok[j];
                    atomicAdd(&out[(size_t)tk * H_DIM + r0],     (a0[j] + bb0) * ww);
                    atomicAdd(&out[(size_t)tk * H_DIM + r0 + 1], (a1[j] + bb1) * ww);
                }
            }
        }
    }
}

// ======================================================================
extern "C" void kernel_launch(void* const* d_in, const int* in_sizes, int n_in,
                              void* d_out, int out_size)
{
    const float* x          = (const float*)d_in[0];
    const float* norm_scale = (const float*)d_in[1];
    const float* gate_w     = (const float*)d_in[2];
    const float* gate_b     = (const float*)d_in[3];
    const float* w1         = (const float*)d_in[4];
    const float* b1         = (const float*)d_in[5];
    const float* w2         = (const float*)d_in[6];
    const float* b2         = (const float*)d_in[7];
    float* out              = (float*)d_out;

    k_route<<<S_TOK, 256>>>(x, norm_scale, gate_w, gate_b, out);
    k_group<<<1, 32>>>();
    k_w1<<<dim3(12, E_NUM), 256>>>(w1, b1);
    k_w2<<<dim3(12, E_NUM), 256>>>(w2, b2, out);
}

// round 4
// speedup vs baseline: 1.5108x; 1.5108x over previous
#include <cuda_runtime.h>
#include <math.h>

#define S_TOK 32
#define H_DIM 768
#define I_DIM 768
#define E_NUM 32
#define K_TOP 4
#define TWO_I 1536
#define LIMIT 7.0f
#define ALPHA 1.702f
#define EPS 1e-5f
#define TMAX 8   // tokens resident in SMEM per pass (zero-padded to mult of 4)

// -------- device scratch --------
__device__ float g_t[S_TOK][H_DIM];
__device__ int   g_topk_idx[S_TOK][K_TOP];
__device__ float g_topk_w[S_TOK][K_TOP];
__device__ int   g_cnt[E_NUM];
__device__ int   g_tok[E_NUM][S_TOK];
__device__ float g_ew[E_NUM][S_TOK];
__device__ float g_act[E_NUM][S_TOK][I_DIM];

// ======================================================================
// Kernel 1: RMSNorm + residual init + router logits + top-4 + softmax
// ======================================================================
__global__ void __launch_bounds__(256) k_route(
    const float* __restrict__ x, const float* __restrict__ norm_scale,
    const float* __restrict__ gate_w, const float* __restrict__ gate_b,
    float* __restrict__ out)
{
    int s   = blockIdx.x;
    int tid = threadIdx.x;
    int lane = tid & 31, warp = tid >> 5;

    __shared__ float sh_t[H_DIM];
    __shared__ float sh_red[8];
    __shared__ float sh_g[E_NUM];

    float ss = 0.f;
    for (int c = tid; c < H_DIM; c += 256) {
        float v = x[s * H_DIM + c];
        sh_t[c] = v;
        out[s * H_DIM + c] = v;          // residual
        ss += v * v;
    }
    #pragma unroll
    for (int o = 16; o; o >>= 1) ss += __shfl_xor_sync(0xffffffffu, ss, o);
    if (lane == 0) sh_red[warp] = ss;
    __syncthreads();
    if (tid < 8) {
        float v = sh_red[tid];
        #pragma unroll
        for (int o = 4; o; o >>= 1) v += __shfl_xor_sync(0xffu, v, o);
        if (tid == 0) sh_red[0] = v;
    }
    __syncthreads();
    float rms = rsqrtf(sh_red[0] / (float)H_DIM + EPS);

    for (int c = tid; c < H_DIM; c += 256) {
        float tv = sh_t[c] * rms * norm_scale[c];
        sh_t[c] = tv;
        g_t[s][c] = tv;
    }
    __syncthreads();

    #pragma unroll
    for (int q = 0; q < 4; q++) {
        int e = warp * 4 + q;
        const float* gwr = gate_w + (size_t)e * H_DIM;
        float acc = 0.f;
        for (int c = lane; c < H_DIM; c += 32) acc += sh_t[c] * gwr[c];
        #pragma unroll
        for (int o = 16; o; o >>= 1) acc += __shfl_xor_sync(0xffffffffu, acc, o);
        if (lane == 0) sh_g[e] = acc + gate_b[e];
    }
    __syncthreads();

    if (tid == 0) {
        bool used[E_NUM];
        #pragma unroll
        for (int e = 0; e < E_NUM; e++) used[e] = false;
        float vals[K_TOP]; int idx[K_TOP];
        for (int k = 0; k < K_TOP; k++) {
            float best = -1e30f; int bi = 0;
            for (int e = 0; e < E_NUM; e++)
                if (!used[e] && sh_g[e] > best) { best = sh_g[e]; bi = e; }
            used[bi] = true; vals[k] = best; idx[k] = bi;
        }
        float m = vals[0], sum = 0.f, w[K_TOP];
        for (int k = 0; k < K_TOP; k++) { w[k] = __expf(vals[k] - m); sum += w[k]; }
        for (int k = 0; k < K_TOP; k++) {
            g_topk_idx[s][k] = idx[k];
            g_topk_w[s][k]   = w[k] / sum;
        }
    }
}

// ======================================================================
// Kernel 2: group (token,k) pairs by expert
// ======================================================================
__global__ void k_group()
{
    if (blockIdx.x == 0 && threadIdx.x == 0) {
        int cnt[E_NUM];
        #pragma unroll
        for (int e = 0; e < E_NUM; e++) cnt[e] = 0;
        for (int s = 0; s < S_TOK; s++)
            for (int k = 0; k < K_TOP; k++) {
                int e = g_topk_idx[s][k];
                int slot = cnt[e]++;
                g_tok[e][slot] = s;
                g_ew[e][slot]  = g_topk_w[s][k];
            }
        for (int e = 0; e < E_NUM; e++) g_cnt[e] = cnt[e];
    }
}

// ======================================================================
// Kernel 3: w1 GEMV + SwiGLU.
// grid = (12, E), 256 thr. Block covers 64 row-PAIRS (128 rows).
// Per row-pair: ALL 12 weight float4 loaded to registers up front
// (MLP=12/warp), then token chunks of 4 (zero-padded) FMA from SMEM.
// Weights read from DRAM exactly once per <=8-token pass.
// ======================================================================
__global__ void __launch_bounds__(256) k_w1(
    const float* __restrict__ w1, const float* __restrict__ b1)
{
    int e = blockIdx.y;
    int cnt = g_cnt[e];
    if (cnt == 0) return;

    int pairbase = blockIdx.x * 64;
    int tid = threadIdx.x, lane = tid & 31, warp = tid >> 5;

    __shared__ float sh_t[TMAX][H_DIM];

    const float* w1e = w1 + (size_t)e * TWO_I * H_DIM;

    for (int p0 = 0; p0 < cnt; p0 += TMAX) {
        int np  = min(TMAX, cnt - p0);
        int np4 = (np + 3) & ~3;               // padded to 4 or 8
        __syncthreads();
        for (int idx = tid; idx < np4 * H_DIM; idx += 256) {
            int j = idx / H_DIM, c = idx - j * H_DIM;
            sh_t[j][c] = (j < np) ? g_t[g_tok[e][p0 + j]][c] : 0.f;
        }
        __syncthreads();

        for (int p = warp; p < 64; p += 8) {
            int pr = pairbase + p;
            int r0 = 2 * pr;
            const float4* wr0 = (const float4*)(w1e + (size_t)r0 * H_DIM);
            const float4* wr1 = (const float4*)(w1e + (size_t)(r0 + 1) * H_DIM);

            // ---- all weight loads issued up front: 12 LDG.128 in flight
            float4 wa[6], wb[6];
            #pragma unroll
            for (int u = 0; u < 6; u++) {
                wa[u] = wr0[lane + 32 * u];
                wb[u] = wr1[lane + 32 * u];
            }

            float bg = b1[(size_t)e * TWO_I + r0];
            float bl = b1[(size_t)e * TWO_I + r0 + 1];

            for (int j0 = 0; j0 < np4; j0 += 4) {
                float a0[4] = {0.f,0.f,0.f,0.f};
                float a1[4] = {0.f,0.f,0.f,0.f};
                #pragma unroll
                for (int u = 0; u < 6; u++) {
                    #pragma unroll
                    for (int j = 0; j < 4; j++) {
                        float4 tv = *(const float4*)&sh_t[j0 + j][(lane + 32 * u) * 4];
                        a0[j] += wa[u].x*tv.x + wa[u].y*tv.y + wa[u].z*tv.z + wa[u].w*tv.w;
                        a1[j] += wb[u].x*tv.x + wb[u].y*tv.y + wb[u].z*tv.z + wb[u].w*tv.w;
                    }
                }
                #pragma unroll
                for (int j = 0; j < 4; j++) {
                    #pragma unroll
                    for (int o = 16; o; o >>= 1) {
                        a0[j] += __shfl_xor_sync(0xffffffffu, a0[j], o);
                        a1[j] += __shfl_xor_sync(0xffffffffu, a1[j], o);
                    }
                }
                #pragma unroll
                for (int j = 0; j < 4; j++) {
                    if (lane == j && j0 + j < np) {
                        float hg = a0[j] + bg;
                        float hl = a1[j] + bl;
                        hg = fminf(hg, LIMIT);
                        hl = fminf(fmaxf(hl, -LIMIT), LIMIT);
                        float sg = 1.f / (1.f + __expf(-ALPHA * hg));
                        g_act[e][p0 + j0 + j][pr] = hg * sg * (hl + 1.f);
                    }
                }
            }
        }
    }
}

// ======================================================================
// Kernel 4: w2 GEMV + weighted atomic accumulate.
// grid = (12, E), 256 thr. Block covers 32 row-pairs (64 rows).
// Same weights-in-registers / token-chunk structure.
// ======================================================================
__global__ void __launch_bounds__(256) k_w2(
    const float* __restrict__ w2, const float* __restrict__ b2,
    float* __restrict__ out)
{
    int e = blockIdx.y;
    int cnt = g_cnt[e];
    if (cnt == 0) return;

    int pairbase = blockIdx.x * 32;
    int tid = threadIdx.x, lane = tid & 31, warp = tid >> 5;

    __shared__ float sh_a[TMAX][I_DIM];
    __shared__ float sh_w[TMAX];
    __shared__ int   sh_tok[TMAX];

    const float* w2e = w2 + (size_t)e * H_DIM * I_DIM;

    for (int p0 = 0; p0 < cnt; p0 += TMAX) {
        int np  = min(TMAX, cnt - p0);
        int np4 = (np + 3) & ~3;
        __syncthreads();
        for (int idx = tid; idx < np4 * I_DIM; idx += 256) {
            int j = idx / I_DIM, c = idx - j * I_DIM;
            sh_a[j][c] = (j < np) ? g_act[e][p0 + j][c] : 0.f;
        }
        if (tid < np) {
            sh_w[tid]   = g_ew[e][p0 + tid];
            sh_tok[tid] = g_tok[e][p0 + tid];
        }
        __syncthreads();

        for (int p = warp; p < 32; p += 8) {
            int r0 = 2 * (pairbase + p);
            const float4* wr0 = (const float4*)(w2e + (size_t)r0 * I_DIM);
            const float4* wr1 = (const float4*)(w2e + (size_t)(r0 + 1) * I_DIM);

            float4 wa[6], wb[6];
            #pragma unroll
            for (int u = 0; u < 6; u++) {
                wa[u] = wr0[lane + 32 * u];
                wb[u] = wr1[lane + 32 * u];
            }

            float bb0 = b2[(size_t)e * H_DIM + r0];
            float bb1 = b2[(size_t)e * H_DIM + r0 + 1];

            for (int j0 = 0; j0 < np4; j0 += 4) {
                float a0[4] = {0.f,0.f,0.f,0.f};
                float a1[4] = {0.f,0.f,0.f,0.f};
                #pragma unroll
                for (int u = 0; u < 6; u++) {
                    #pragma unroll
                    for (int j = 0; j < 4; j++) {
                        float4 av = *(const float4*)&sh_a[j0 + j][(lane + 32 * u) * 4];
                        a0[j] += wa[u].x*av.x + wa[u].y*av.y + wa[u].z*av.z + wa[u].w*av.w;
                        a1[j] += wb[u].x*av.x + wb[u].y*av.y + wb[u].z*av.z + wb[u].w*av.w;
                    }
                }
                #pragma unroll
                for (int j = 0; j < 4; j++) {
                    #pragma unroll
                    for (int o = 16; o; o >>= 1) {
                        a0[j] += __shfl_xor_sync(0xffffffffu, a0[j], o);
                        a1[j] += __shfl_xor_sync(0xffffffffu, a1[j], o);
                    }
                }
                #pragma unroll
                for (int j = 0; j < 4; j++) {
                    if (lane == j && j0 + j < np) {
                        float ww = sh_w[j0 + j];
                        int   tk = sh_tok[j0 + j];
                        atomicAdd(&out[(size_t)tk * H_DIM + r0],     (a0[j] + bb0) * ww);
                        atomicAdd(&out[(size_t)tk * H_DIM + r0 + 1], (a1[j] + bb1) * ww);
                    }
                }
            }
        }
    }
}

// ======================================================================
extern "C" void kernel_launch(void* const* d_in, const int* in_sizes, int n_in,
                              void* d_out, int out_size)
{
    const float* x          = (const float*)d_in[0];
    const float* norm_scale = (const float*)d_in[1];
    const float* gate_w     = (const float*)d_in[2];
    const float* gate_b     = (const float*)d_in[3];
    const float* w1         = (const float*)d_in[4];
    const float* b1         = (const float*)d_in[5];
    const float* w2         = (const float*)d_in[6];
    const float* b2         = (const float*)d_in[7];
    float* out              = (float*)d_out;

    k_route<<<S_TOK, 256>>>(x, norm_scale, gate_w, gate_b, out);
    k_group<<<1, 32>>>();
    k_w1<<<dim3(12, E_NUM), 256>>>(w1, b1);
    k_w2<<<dim3(12, E_NUM), 256>>>(w2, b2, out);
}